// round 9
// baseline (speedup 1.0000x reference)
#include <cuda_runtime.h>
#include <cuda_bf16.h>
#include <cstdint>

// ---------------- problem constants ----------------
#define MDIM 4096
#define NDIM 4096
#define KDIM 4096
// zero points: X_ZP = -66, Y_ZP = 160
// (x - zx)(y - zy) summed over K:
//   dot(x,y) - 160*rowsum(x) + 66*colsum(y) + K*zx*zy
#define KZZ (-43253760)          // 4096 * (-66) * 160
#define OUT_SCALE (0.03f * 0.025f)

// ---------------- scratch ----------------
__device__ unsigned char g_xa[(size_t)MDIM * KDIM];   // x packed s8, row-major [M,K]
__device__ unsigned char g_yb[(size_t)NDIM * KDIM];   // y packed u8, K-major [N,K]
__device__ int g_rx[MDIM];                            // rowsum of x, premultiplied by 160
__device__ int g_cy[NDIM];                            // colsum of y

// ---------------- merged conversion kernel (unchanged from R6) ----------------
__global__ __launch_bounds__(256) void conv_kernel(const int* __restrict__ x,
                                                   const int* __restrict__ y) {
    int b = blockIdx.x;
    int tid = threadIdx.x;
    if (b < MDIM) {
        int row = b;
        const int4* src = reinterpret_cast<const int4*>(x + (size_t)row * KDIM) + tid * 4;
        int sum = 0;
        unsigned int packed[4];
        #pragma unroll
        for (int i = 0; i < 4; i++) {
            int4 v = src[i];
            sum += v.x + v.y + v.z + v.w;
            packed[i] = (v.x & 0xFF) | ((v.y & 0xFF) << 8) | ((v.z & 0xFF) << 16) | ((v.w & 0xFF) << 24);
        }
        uint4 o = make_uint4(packed[0], packed[1], packed[2], packed[3]);
        reinterpret_cast<uint4*>(g_xa + (size_t)row * KDIM)[tid] = o;

        #pragma unroll
        for (int s = 16; s > 0; s >>= 1) sum += __shfl_down_sync(0xFFFFFFFF, sum, s);
        __shared__ int warp_s[8];
        if ((tid & 31) == 0) warp_s[tid >> 5] = sum;
        __syncthreads();
        if (tid == 0) {
            int t = 0;
            #pragma unroll
            for (int w = 0; w < 8; w++) t += warp_s[w];
            g_rx[row] = t * 160;
        }
    } else {
        int t0 = b - MDIM;               // 0..4095
        int n0 = (t0 & 127) * 32;
        int k0 = (t0 >> 7) * 128;
        int tx = tid & 31;
        int ty = tid >> 5;
        __shared__ unsigned int sh32[32][33];
        __shared__ int red[8][32];
        unsigned char* shb = reinterpret_cast<unsigned char*>(sh32);
        int csum = 0;
        #pragma unroll
        for (int r = 0; r < 16; r++) {
            int kk = ty + r * 8;
            int v = y[(size_t)(k0 + kk) * NDIM + n0 + tx];
            csum += v;
            shb[tx * 132 + kk] = (unsigned char)v;
        }
        red[ty][tx] = csum;
        __syncthreads();
        int n = tid >> 3;
        int wq = tid & 7;
        uint4 o;
        o.x = sh32[n][wq * 4 + 0];
        o.y = sh32[n][wq * 4 + 1];
        o.z = sh32[n][wq * 4 + 2];
        o.w = sh32[n][wq * 4 + 3];
        *reinterpret_cast<uint4*>(&g_yb[(size_t)(n0 + n) * KDIM + k0 + wq * 16]) = o;
        if (ty == 0) {
            int s = 0;
            #pragma unroll
            for (int w = 0; w < 8; w++) s += red[w][tx];
            atomicAdd(&g_cy[n0 + tx], s);
        }
    }
}

// ---------------- GEMM (s8 x u8 -> s32 via mma.sync) ----------------
// 128x64 CTA tile, 3 CTAs/SM, 8 warps in 2(M) x 4(N), warp tile 64x16
static constexpr int BM = 128;
static constexpr int BN = 64;
static constexpr int BKB = 128;                  // k bytes per chunk
static constexpr int NCHUNK = KDIM / BKB;        // 32
static constexpr int STAGES = 3;
static constexpr int A_TILE = BM * BKB;          // 16384
static constexpr int B_TILE = BN * BKB;          // 8192
static constexpr int STAGE_BYTES = A_TILE + B_TILE;          // 24576
static constexpr int CORR_OFF = STAGES * STAGE_BYTES;        // 73728
static constexpr int SMEM_TOTAL = CORR_OFF + 1024;           // 74752 (x3 = 224256 <= 228KB)

__device__ __forceinline__ uint32_t smem_to_u32(const void* p) {
    uint32_t a;
    asm("{ .reg .u64 t; cvta.to.shared.u64 t, %1; cvt.u32.u64 %0, t; }" : "=r"(a) : "l"(p));
    return a;
}

#define LDSM_X4(r0, r1, r2, r3, addr) \
    asm volatile("ldmatrix.sync.aligned.m8n8.x4.shared.b16 {%0,%1,%2,%3}, [%4];" \
        : "=r"(r0), "=r"(r1), "=r"(r2), "=r"(r3) : "r"(addr))

#define MMA_S8U8(d, a, b0, b1) \
    asm volatile("mma.sync.aligned.m16n8k32.row.col.s32.s8.u8.s32 " \
        "{%0,%1,%2,%3}, {%4,%5,%6,%7}, {%8,%9}, {%0,%1,%2,%3};" \
        : "+r"((d)[0]), "+r"((d)[1]), "+r"((d)[2]), "+r"((d)[3]) \
        : "r"((a)[0]), "r"((a)[1]), "r"((a)[2]), "r"((a)[3]), "r"(b0), "r"(b1))

#define CP_ASYNC16(dst, src) \
    asm volatile("cp.async.cg.shared.global [%0], [%1], 16;\n" :: "r"(dst), "l"(src))
#define CP_COMMIT()  asm volatile("cp.async.commit_group;\n" ::: "memory")
#define CP_WAIT1()   asm volatile("cp.async.wait_group 1;\n" ::: "memory")
#define CP_WAIT0()   asm volatile("cp.async.wait_group 0;\n" ::: "memory")

__global__ __launch_bounds__(256, 3) void gemm_s8_kernel(float* __restrict__ out) {
    extern __shared__ __align__(1024) char smem[];
    uint32_t sb = smem_to_u32(smem);
    int tid  = threadIdx.x;
    int wid  = tid >> 5;
    int lane = tid & 31;

    int m0 = blockIdx.y * BM;
    int n0 = blockIdx.x * BN;
    int wm = (wid >> 2) * 64;      // warp M offset (2 rows of warps)
    int wn = (wid & 3) * 16;       // warp N offset (4 cols of warps)

    const char* gA = reinterpret_cast<const char*>(g_xa) + (size_t)m0 * KDIM;
    const char* gB = reinterpret_cast<const char*>(g_yb) + (size_t)n0 * KDIM;

    // stash corrections in smem (published by the first main-loop barrier)
    int* sRX = reinterpret_cast<int*>(smem + CORR_OFF);
    int* sCY = sRX + 128;
    if (tid < 128) {
        sRX[tid] = __ldg(&g_rx[m0 + tid]);                    // already *160
    } else if (tid < 192) {
        sCY[tid - 128] = __ldg(&g_cy[n0 + (tid - 128)]) * 66 + KZZ;
    }

    // per-thread cp.async geometry: 6 x 16B per stage (A: 1024 chunks, B: 512)
    const char* cp_src[6];
    uint32_t cp_dst[6];
    #pragma unroll
    for (int i = 0; i < 6; i++) {
        int idx = tid + i * 256;          // 0..1535
        int which = (idx >= 1024);        // 0=A, 1=B
        int j = which ? (idx - 1024) : idx;
        int row = j >> 3;
        int c16 = (j & 7) * 16;
        uint32_t off = (uint32_t)(row * BKB + c16);
        cp_dst[i] = (uint32_t)(which ? A_TILE : 0) + (off ^ ((off >> 3) & 0x70));
        cp_src[i] = (which ? gB : gA) + (size_t)row * KDIM + c16;
    }

    // ldmatrix per-thread bases
    int rA = ((lane >> 3) & 1) * 8 + (lane & 7);
    int kA = ((lane >> 4) & 1) * 16;
    uint32_t offA_lin = (uint32_t)((wm + rA) * BKB + kA);
    int rB = ((lane >> 4) & 1) * 8 + (lane & 7);
    int kB = ((lane >> 3) & 1) * 16;
    uint32_t offB_lin = (uint32_t)((wn + rB) * BKB + kB);
    uint32_t xmA = (uint32_t)((rA & 7) << 4);
    uint32_t xmB = (uint32_t)((rB & 7) << 4);

    int d[4][2][4];
    #pragma unroll
    for (int mi = 0; mi < 4; mi++)
        #pragma unroll
        for (int ni = 0; ni < 2; ni++)
            #pragma unroll
            for (int r = 0; r < 4; r++) d[mi][ni][r] = 0;

    auto load_chunk = [&](int c, int s) {
        uint32_t base = sb + (uint32_t)s * STAGE_BYTES;
        size_t koff = (size_t)c * BKB;
        #pragma unroll
        for (int i = 0; i < 6; i++) {
            CP_ASYNC16(base + cp_dst[i], cp_src[i] + koff);
        }
        CP_COMMIT();
    };

    load_chunk(0, 0);
    load_chunk(1, 1);

    #pragma unroll 1
    for (int c = 0; c < NCHUNK; c++) {
        if (c < NCHUNK - 1) CP_WAIT1();
        else                CP_WAIT0();
        __syncthreads();   // publishes chunk c; retires last iter's reads of slot (c+2)%3

        if (c + 2 < NCHUNK) load_chunk(c + 2, (c + 2) % STAGES);

        int s = c % STAGES;
        uint32_t stA = sb + (uint32_t)s * STAGE_BYTES;
        uint32_t stB = stA + A_TILE;

        #pragma unroll
        for (int ks = 0; ks < 4; ks++) {
            uint32_t a[4][4];
            #pragma unroll
            for (int mi = 0; mi < 4; mi++) {
                uint32_t addr = stA + ((offA_lin + (uint32_t)(mi * 2048 + ks * 32)) ^ xmA);
                LDSM_X4(a[mi][0], a[mi][1], a[mi][2], a[mi][3], addr);
            }
            uint32_t b[2][2];
            {
                uint32_t addr = stB + ((offB_lin + (uint32_t)(ks * 32)) ^ xmB);
                LDSM_X4(b[0][0], b[0][1], b[1][0], b[1][1], addr);
            }
            #pragma unroll
            for (int mi = 0; mi < 4; mi++)
                #pragma unroll
                for (int ni = 0; ni < 2; ni++)
                    MMA_S8U8(d[mi][ni], a[mi], b[ni][0], b[ni][1]);
        }
    }

    // ---------------- epilogue: zero-point correction + scale (smem-fed) ----------------
    const float S = OUT_SCALE;
    int rlo = lane >> 2;
    int cc  = (lane & 3) * 2;
    #pragma unroll
    for (int mi = 0; mi < 4; mi++) {
        int lrow = wm + mi * 16 + rlo;
        int row0 = m0 + lrow;
        int rxa = sRX[lrow];
        int rxb = sRX[lrow + 8];
        #pragma unroll
        for (int ni = 0; ni < 2; ni++) {
            int lcol = wn + ni * 8 + cc;
            int col = n0 + lcol;
            int cy0 = sCY[lcol];
            int cy1 = sCY[lcol + 1];
            const int* dd = d[mi][ni];
            float2 v0, v1;
            v0.x = S * (float)(dd[0] - rxa + cy0);
            v0.y = S * (float)(dd[1] - rxa + cy1);
            v1.x = S * (float)(dd[2] - rxb + cy0);
            v1.y = S * (float)(dd[3] - rxb + cy1);
            *reinterpret_cast<float2*>(out + (size_t)row0 * NDIM + col) = v0;
            *reinterpret_cast<float2*>(out + (size_t)(row0 + 8) * NDIM + col) = v1;
        }
    }
}

// ---------------- launch ----------------
extern "C" void kernel_launch(void* const* d_in, const int* in_sizes, int n_in,
                              void* d_out, int out_size) {
    const int* x = (const int*)d_in[0];   // [M, K] int32 (int8-range)
    const int* y = (const int*)d_in[1];   // [K, N] int32 (uint8-range)
    float* out = (float*)d_out;

    // zero g_cy via a memset node (no allocation)
    void* cy_ptr = nullptr;
    cudaGetSymbolAddress(&cy_ptr, g_cy);
    cudaMemsetAsync(cy_ptr, 0, NDIM * sizeof(int), 0);

    conv_kernel<<<MDIM + 4096, 256>>>(x, y);

    cudaFuncSetAttribute(gemm_s8_kernel, cudaFuncAttributeMaxDynamicSharedMemorySize, SMEM_TOTAL);
    gemm_s8_kernel<<<dim3(NDIM / BN, MDIM / BM), 256, SMEM_TOTAL>>>(out);
}